// round 16
// baseline (speedup 1.0000x reference)
#include <cuda_runtime.h>
#include <cuda_bf16.h>
#include <cstdint>

// ---------------------------------------------------------------------------
// MultiheadRelativeAttention: B=4, T=1024, E=1024, H=16, D=64, MAX_REL=128
// Round 16: attn2 exp/scatter loops merged (halve index ALU); cvt_add_split
// fused into w2_gemm epilogue (writes bf16 split of c1+c2 directly).
// ---------------------------------------------------------------------------

#define MROWS 4096      // B*T
#define EDIM  1024
#define RSTR  260       // padded stride for 257 relative positions
#define ASTRIDE 320     // padded K for w2 gemm

typedef unsigned long long u64t;

__device__ float g_B [64 * 1024 * RSTR];   // bias table per source slot (log2 units)
__device__ float g_c1[MROWS * EDIM];

__device__ __nv_bfloat16 g_Xh[MROWS * EDIM];
__device__ __nv_bfloat16 g_Xl[MROWS * EDIM];
__device__ __nv_bfloat16 g_Wqh[EDIM * EDIM], g_Wql[EDIM * EDIM];
__device__ __nv_bfloat16 g_Wkh[EDIM * EDIM], g_Wkl[EDIM * EDIM];
__device__ __nv_bfloat16 g_Wvh[EDIM * EDIM], g_Wvl[EDIM * EDIM];
__device__ __nv_bfloat16 g_Woh[EDIM * EDIM], g_Wol[EDIM * EDIM];
__device__ __nv_bfloat16 g_Qbh[MROWS * EDIM], g_Qbl[MROWS * EDIM];
__device__ __nv_bfloat16 g_Kbh[MROWS * EDIM];   // K single
__device__ __nv_bfloat16 g_Vbh[MROWS * EDIM];   // V single
__device__ __nv_bfloat16 g_Rkh[320 * 64], g_Rkl[320 * 64];
__device__ __nv_bfloat16 g_A2h[64 * 1024 * ASTRIDE], g_A2l[64 * 1024 * ASTRIDE];
__device__ __nv_bfloat16 g_Rvh[64 * ASTRIDE], g_Rvl[64 * ASTRIDE];

// ---------------------------------------------------------------------------
// helpers
// ---------------------------------------------------------------------------
__device__ __forceinline__ uint32_t smem_to_u32(const void* p) {
    uint32_t a;
    asm("{ .reg .u64 t; cvta.to.shared.u64 t, %1; cvt.u32.u64 %0, t; }" : "=r"(a) : "l"(p));
    return a;
}
__device__ __forceinline__ void cpasync16(uint32_t dst, const void* src) {
    asm volatile("cp.async.cg.shared.global [%0], [%1], 16;" :: "r"(dst), "l"(src));
}
#define CP_COMMIT() asm volatile("cp.async.commit_group;" ::: "memory")
#define CP_WAIT(n)  asm volatile("cp.async.wait_group %0;" :: "n"(n) : "memory")

__device__ __forceinline__ void ldsm4(uint32_t* r, uint32_t addr) {
    asm volatile("ldmatrix.sync.aligned.m8n8.x4.shared.b16 {%0,%1,%2,%3}, [%4];"
                 : "=r"(r[0]), "=r"(r[1]), "=r"(r[2]), "=r"(r[3]) : "r"(addr));
}
__device__ __forceinline__ void ldsm4t(uint32_t* r, uint32_t addr) {
    asm volatile("ldmatrix.sync.aligned.m8n8.x4.trans.shared.b16 {%0,%1,%2,%3}, [%4];"
                 : "=r"(r[0]), "=r"(r[1]), "=r"(r[2]), "=r"(r[3]) : "r"(addr));
}
__device__ __forceinline__ void mma16816(float* c, const uint32_t* a, uint32_t b0, uint32_t b1) {
    asm volatile("mma.sync.aligned.m16n8k16.row.col.f32.bf16.bf16.f32 "
                 "{%0,%1,%2,%3}, {%4,%5,%6,%7}, {%8,%9}, {%0,%1,%2,%3};"
                 : "+f"(c[0]), "+f"(c[1]), "+f"(c[2]), "+f"(c[3])
                 : "r"(a[0]), "r"(a[1]), "r"(a[2]), "r"(a[3]), "r"(b0), "r"(b1));
}
__device__ __forceinline__ uint32_t pack_bf2(__nv_bfloat16 lo, __nv_bfloat16 hi) {
    return ((uint32_t)__bfloat16_as_ushort(hi) << 16) | (uint32_t)__bfloat16_as_ushort(lo);
}

// ---------------------------------------------------------------------------
// merged input conversions
// ---------------------------------------------------------------------------
struct CvtParams {
    const float *X, *Wq, *Wk, *Wv, *Wo, *relk, *relv;
    __nv_bfloat16 *Xh, *Xl, *Wqh, *Wql, *Wkh, *Wkl, *Wvh, *Wvl, *Woh, *Wol;
    __nv_bfloat16 *Rkh, *Rkl, *Rvh, *Rvl;
};

__device__ __forceinline__ void split4(const float* __restrict__ src,
                                       __nv_bfloat16* __restrict__ hi,
                                       __nv_bfloat16* __restrict__ lo, int i)
{
    float4 v = *(const float4*)(src + i);
    __nv_bfloat16 h0 = __float2bfloat16(v.x), h1 = __float2bfloat16(v.y);
    __nv_bfloat16 h2 = __float2bfloat16(v.z), h3 = __float2bfloat16(v.w);
    ((uint32_t*)(hi + i))[0] = pack_bf2(h0, h1);
    ((uint32_t*)(hi + i))[1] = pack_bf2(h2, h3);
    ((uint32_t*)(lo + i))[0] = pack_bf2(__float2bfloat16(v.x - __bfloat162float(h0)),
                                        __float2bfloat16(v.y - __bfloat162float(h1)));
    ((uint32_t*)(lo + i))[1] = pack_bf2(__float2bfloat16(v.z - __bfloat162float(h2)),
                                        __float2bfloat16(v.w - __bfloat162float(h3)));
}

__global__ __launch_bounds__(256)
void cvt_all(CvtParams p)
{
    const int bid = blockIdx.x;
    if (bid < 4096) {
        split4(p.X, p.Xh, p.Xl, (bid * 256 + threadIdx.x) * 4);
    } else if (bid < 8192) {
        const int w = (bid - 4096) >> 10;
        const int lb = (bid - 4096) & 1023;
        const int i = (lb * 256 + threadIdx.x) * 4;
        if (w == 0)      split4(p.Wq, p.Wqh, p.Wql, i);
        else if (w == 1) split4(p.Wk, p.Wkh, p.Wkl, i);
        else if (w == 2) split4(p.Wv, p.Wvh, p.Wvl, i);
        else             split4(p.Wo, p.Woh, p.Wol, i);
    } else if (bid < 8212) {
        const int base = (bid - 8192) * 1024 + threadIdx.x * 4;
#pragma unroll
        for (int k = 0; k < 4; k++) {
            const int i = base + k;
            if (i >= 320 * 64) break;
            const int r = i >> 6, d = i & 63;
            const float v = (r < 257) ? p.relk[r * 64 + d] : 0.f;
            const __nv_bfloat16 h = __float2bfloat16(v);
            p.Rkh[i] = h;
            p.Rkl[i] = __float2bfloat16(v - __bfloat162float(h));
        }
    } else {
        const int base = (bid - 8212) * 1024 + threadIdx.x * 4;
#pragma unroll
        for (int k = 0; k < 4; k++) {
            const int i = base + k;
            if (i >= 64 * ASTRIDE) break;
            const int d = i / ASTRIDE, r = i % ASTRIDE;
            const float v = (r < 257) ? p.relv[r * 64 + d] : 0.f;
            const __nv_bfloat16 h = __float2bfloat16(v);
            p.Rvh[i] = h;
            p.Rvl[i] = __float2bfloat16(v - __bfloat162float(h));
        }
    }
}

// ---------------------------------------------------------------------------
// GEMM core (round-8 proven)
// ---------------------------------------------------------------------------
#define GSTAGE 65536
#define GSMEM  (3 * GSTAGE)

__device__ __forceinline__ void gemm_core(
    const __nv_bfloat16* __restrict__ Ah, const __nv_bfloat16* __restrict__ Al,
    const __nv_bfloat16* __restrict__ Bh, const __nv_bfloat16* __restrict__ Bl,
    const float* __restrict__ bias, float* __restrict__ C, float alpha,
    __nv_bfloat16* __restrict__ ohi, __nv_bfloat16* __restrict__ olo)
{
    extern __shared__ char smem[];
    const uint32_t sb = smem_to_u32(smem);
    const int tid = threadIdx.x;
    const int wid = tid >> 5, lane = tid & 31;
    const int wm = wid >> 1, wn = wid & 1;
    const int n0 = blockIdx.x * 128, m0 = blockIdx.y * 128;

    float acc[2][8][4];
#pragma unroll
    for (int f = 0; f < 2; f++)
#pragma unroll
        for (int nf = 0; nf < 8; nf++)
#pragma unroll
            for (int e = 0; e < 4; e++) acc[f][nf][e] = 0.f;

    auto issue = [&](int stage, int c) {
        const uint32_t tbs = sb + stage * GSTAGE;
        const int k0 = c * 64;
#pragma unroll
        for (int g = 0; g < 4; g++) {
            const int gi = g * 256 + tid;
            const int row = gi >> 3, gc = gi & 7;
            const uint32_t bo = row * 128 + gc * 16;
            const uint32_t sw = bo ^ ((bo >> 3) & 0x70);
            const size_t aoff = (size_t)(m0 + row) * EDIM + k0 + gc * 8;
            const size_t boff = (size_t)(n0 + row) * EDIM + k0 + gc * 8;
            cpasync16(tbs + sw,         Ah + aoff);
            cpasync16(tbs + 16384 + sw, Al + aoff);
            cpasync16(tbs + 32768 + sw, Bh + boff);
            cpasync16(tbs + 49152 + sw, Bl + boff);
        }
        CP_COMMIT();
    };

    issue(0, 0);
    issue(1, 1);

    const int arow = lane & 15;
    const int achk = lane >> 4;

    uint32_t fah[2][2][4], fal[2][2][4], fbh[2][4][4], fbl[2][4][4];
    auto ldfrag = [&](int buf, int kk, uint32_t st) {
        const int chS = (kk * 2 + achk) ^ (arow & 7);
#pragma unroll
        for (int f = 0; f < 2; f++) {
            const uint32_t ra = st + (uint32_t)(wm * 32 + f * 16 + arow) * 128 + chS * 16;
            ldsm4(fah[buf][f], ra);
            ldsm4(fal[buf][f], ra + 16384);
        }
#pragma unroll
        for (int nb = 0; nb < 4; nb++) {
            const uint32_t rb = st + 32768 + (uint32_t)(wn * 64 + nb * 16 + arow) * 128 + chS * 16;
            ldsm4(fbh[buf][nb], rb);
            ldsm4(fbl[buf][nb], rb + 16384);
        }
    };

    for (int c = 0; c < 16; c++) {
        if (c + 2 < 16) issue((c + 2) % 3, c + 2);
        if (c <= 13)      { CP_WAIT(2); }
        else if (c == 14) { CP_WAIT(1); }
        else              { CP_WAIT(0); }
        __syncthreads();

        const uint32_t st = sb + (c % 3) * GSTAGE;
        ldfrag(0, 0, st);
#pragma unroll
        for (int kk = 0; kk < 4; kk++) {
            const int cur = kk & 1;
            if (kk < 3) ldfrag(cur ^ 1, kk + 1, st);
#pragma unroll
            for (int f = 0; f < 2; f++)
#pragma unroll
                for (int nb = 0; nb < 4; nb++)
#pragma unroll
                    for (int h = 0; h < 2; h++) {
                        float* cc = acc[f][nb * 2 + h];
                        mma16816(cc, fah[cur][f], fbh[cur][nb][h], fbh[cur][nb][h + 2]);
                        mma16816(cc, fah[cur][f], fbl[cur][nb][h], fbl[cur][nb][h + 2]);
                        mma16816(cc, fal[cur][f], fbh[cur][nb][h], fbh[cur][nb][h + 2]);
                    }
        }
        __syncthreads();
    }

    const int gid = lane >> 2, tig = lane & 3;
#pragma unroll
    for (int f = 0; f < 2; f++) {
        const int m = m0 + wm * 32 + f * 16 + gid;
#pragma unroll
        for (int nb = 0; nb < 4; nb++)
#pragma unroll
            for (int h = 0; h < 2; h++) {
                const int n = n0 + wn * 64 + nb * 16 + h * 8 + tig * 2;
                const float* cc = acc[f][nb * 2 + h];
                const float b0 = __ldg(&bias[n]), b1 = __ldg(&bias[n + 1]);
                float2 v0 = make_float2(alpha * (cc[0] + b0), alpha * (cc[1] + b1));
                float2 v1 = make_float2(alpha * (cc[2] + b0), alpha * (cc[3] + b1));
                if (C) {
                    *(float2*)&C[(size_t)m * EDIM + n]       = v0;
                    *(float2*)&C[(size_t)(m + 8) * EDIM + n] = v1;
                }
                __nv_bfloat16 h00 = __float2bfloat16(v0.x), h01 = __float2bfloat16(v0.y);
                __nv_bfloat16 h10 = __float2bfloat16(v1.x), h11 = __float2bfloat16(v1.y);
                if (ohi) {
                    *(uint32_t*)(ohi + (size_t)m * EDIM + n)       = pack_bf2(h00, h01);
                    *(uint32_t*)(ohi + (size_t)(m + 8) * EDIM + n) = pack_bf2(h10, h11);
                }
                if (olo) {
                    *(uint32_t*)(olo + (size_t)m * EDIM + n) =
                        pack_bf2(__float2bfloat16(v0.x - __bfloat162float(h00)),
                                 __float2bfloat16(v0.y - __bfloat162float(h01)));
                    *(uint32_t*)(olo + (size_t)(m + 8) * EDIM + n) =
                        pack_bf2(__float2bfloat16(v1.x - __bfloat162float(h10)),
                                 __float2bfloat16(v1.y - __bfloat162float(h11)));
                }
            }
    }
}

__global__ __launch_bounds__(256, 1)
void mma_gemm(const __nv_bfloat16* __restrict__ Ah, const __nv_bfloat16* __restrict__ Al,
              const __nv_bfloat16* __restrict__ Bh, const __nv_bfloat16* __restrict__ Bl,
              const float* __restrict__ bias, float* __restrict__ C, float alpha,
              __nv_bfloat16* __restrict__ ohi, __nv_bfloat16* __restrict__ olo)
{
    gemm_core(Ah, Al, Bh, Bl, bias, C, alpha, ohi, olo);
}

struct G3Params {
    const __nv_bfloat16* Bh[3]; const __nv_bfloat16* Bl[3];
    const float* bias[3];
    __nv_bfloat16* oh[3]; __nv_bfloat16* ol[3];
    float alpha[3];
};
__global__ __launch_bounds__(256, 1)
void mma_gemm3(const __nv_bfloat16* __restrict__ Ah, const __nv_bfloat16* __restrict__ Al,
               G3Params p)
{
    const int z = blockIdx.z;
    gemm_core(Ah, Al, p.Bh[z], p.Bl[z], p.bias[z], nullptr, p.alpha[z], p.oh[z], p.ol[z]);
}

// ---------------------------------------------------------------------------
// w2_gemm: computes c2 = A2 @ Rvt^T, then fuses c1+c2 and emits the bf16
// split of the sum directly into the Wo-GEMM input buffers (Xh/Xl).
// ---------------------------------------------------------------------------
#define W2_AOFF  81920
#define W2_SMEM  (81920 + 2 * 32768)   // 147456

__global__ __launch_bounds__(256, 1)
void w2_gemm(const __nv_bfloat16* __restrict__ A2h, const __nv_bfloat16* __restrict__ A2l,
             const __nv_bfloat16* __restrict__ Rvh, const __nv_bfloat16* __restrict__ Rvl,
             const float* __restrict__ c1,
             __nv_bfloat16* __restrict__ ohi, __nv_bfloat16* __restrict__ olo)
{
    extern __shared__ char smem[];
    const uint32_t sb = smem_to_u32(smem);
    const int tid = threadIdx.x;
    const int wid = tid >> 5, lane = tid & 31;
    const int wm = wid >> 1, wn = wid & 1;
    const int m0 = blockIdx.x * 128;
    const int arow = lane & 15, achk = lane >> 4;

    auto issueA = [&](int stage, int c) {
        const uint32_t base = sb + W2_AOFF + stage * 32768;
#pragma unroll
        for (int g = 0; g < 4; g++) {
            const int gi = g * 256 + tid;
            const int row = gi >> 3, gc = gi & 7;
            const uint32_t bo = row * 128 + gc * 16;
            const uint32_t sw = bo ^ ((bo >> 3) & 0x70);
            const size_t off = (size_t)(m0 + row) * ASTRIDE + c * 64 + gc * 8;
            cpasync16(base + sw,         A2h + off);
            cpasync16(base + 16384 + sw, A2l + off);
        }
    };

#pragma unroll
    for (int c = 0; c < 5; c++) {
#pragma unroll
        for (int g = 0; g < 2; g++) {
            const int gi = g * 256 + tid;
            const int row = gi >> 3, gc = gi & 7;
            const uint32_t bo = row * 128 + gc * 16;
            const uint32_t sw = bo ^ ((bo >> 3) & 0x70);
            const size_t off = (size_t)row * ASTRIDE + c * 64 + gc * 8;
            cpasync16(sb + c * 16384 + sw,        Rvh + off);
            cpasync16(sb + c * 16384 + 8192 + sw, Rvl + off);
        }
    }
    issueA(0, 0);
    CP_COMMIT();
    issueA(1, 1);
    CP_COMMIT();

    float acc[2][4][4];
#pragma unroll
    for (int f = 0; f < 2; f++)
#pragma unroll
        for (int nf = 0; nf < 4; nf++)
#pragma unroll
            for (int e = 0; e < 4; e++) acc[f][nf][e] = 0.f;

    for (int c = 0; c < 5; c++) {
        if (c < 4) { CP_WAIT(1); } else { CP_WAIT(0); }
        __syncthreads();
        const uint32_t stA = sb + W2_AOFF + (c & 1) * 32768;
        const uint32_t stB = sb + c * 16384;
#pragma unroll
        for (int kk = 0; kk < 4; kk++) {
            const int chS = (kk * 2 + achk) ^ (arow & 7);
            uint32_t ah[2][4], al[2][4], bh[2][4], bl[2][4];
#pragma unroll
            for (int f = 0; f < 2; f++) {
                const uint32_t ra = stA + (uint32_t)(wm * 32 + f * 16 + arow) * 128 + chS * 16;
                ldsm4(ah[f], ra);
                ldsm4(al[f], ra + 16384);
            }
#pragma unroll
            for (int nb = 0; nb < 2; nb++) {
                const uint32_t rb = stB + (uint32_t)(wn * 32 + nb * 16 + arow) * 128 + chS * 16;
                ldsm4(bh[nb], rb);
                ldsm4(bl[nb], rb + 8192);
            }
#pragma unroll
            for (int f = 0; f < 2; f++)
#pragma unroll
                for (int nb = 0; nb < 2; nb++)
#pragma unroll
                    for (int h = 0; h < 2; h++) {
                        float* cc = acc[f][nb * 2 + h];
                        mma16816(cc, ah[f], bh[nb][h], bh[nb][h + 2]);
                        mma16816(cc, ah[f], bl[nb][h], bl[nb][h + 2]);
                        mma16816(cc, al[f], bh[nb][h], bh[nb][h + 2]);
                    }
        }
        __syncthreads();
        if (c + 2 < 5) { issueA(c & 1, c + 2); CP_COMMIT(); }
    }

    const int gid = lane >> 2, tig = lane & 3;
#pragma unroll
    for (int f = 0; f < 2; f++) {
        const int m = m0 + wm * 32 + f * 16 + gid;
        const int slot = m >> 10, q = m & 1023;
        const int b2 = slot & 3, h2 = slot >> 2;      // sigma^-1(slot)
        const size_t row0 = (size_t)(b2 * 1024 + q) * EDIM + h2 * 64;
        const size_t row1 = (size_t)(b2 * 1024 + q + 8) * EDIM + h2 * 64;
#pragma unroll
        for (int nb = 0; nb < 2; nb++)
#pragma unroll
            for (int h = 0; h < 2; h++) {
                const int n = wn * 32 + nb * 16 + h * 8 + tig * 2;
                const float* cc = acc[f][nb * 2 + h];
                const float2 a0 = *(const float2*)&c1[row0 + n];
                const float2 a1 = *(const float2*)&c1[row1 + n];
                const float v0x = a0.x + cc[0], v0y = a0.y + cc[1];
                const float v1x = a1.x + cc[2], v1y = a1.y + cc[3];
                const __nv_bfloat16 h00 = __float2bfloat16(v0x), h01 = __float2bfloat16(v0y);
                const __nv_bfloat16 h10 = __float2bfloat16(v1x), h11 = __float2bfloat16(v1y);
                *(uint32_t*)(ohi + row0 + n) = pack_bf2(h00, h01);
                *(uint32_t*)(ohi + row1 + n) = pack_bf2(h10, h11);
                *(uint32_t*)(olo + row0 + n) =
                    pack_bf2(__float2bfloat16(v0x - __bfloat162float(h00)),
                             __float2bfloat16(v0y - __bfloat162float(h01)));
                *(uint32_t*)(olo + row1 + n) =
                    pack_bf2(__float2bfloat16(v1x - __bfloat162float(h10)),
                             __float2bfloat16(v1y - __bfloat162float(h11)));
            }
    }
}

// ---------------------------------------------------------------------------
// Bias table via mma, r-tiles looped in-CTA (round 12, unchanged)
// ---------------------------------------------------------------------------
#define BIAS_SMEM 49152
__global__ __launch_bounds__(128, 1)
void bias_mma(const __nv_bfloat16* __restrict__ Qbh, const __nv_bfloat16* __restrict__ Qbl,
              const __nv_bfloat16* __restrict__ Rh, const __nv_bfloat16* __restrict__ Rl,
              float* __restrict__ Bt)
{
    extern __shared__ char smem[];
    const uint32_t sb = smem_to_u32(smem);
    const int jslot = blockIdx.y;
    const int bb = jslot >> 4, hh = jslot & 15;
    const int q0 = blockIdx.x * 64;
    const int tid = threadIdx.x, wid = tid >> 5, lane = tid & 31;
    const int wm = wid >> 1, wn = wid & 1;
    const int arow = lane & 15, ahalf = lane >> 4;

    auto issueR = [&](int stg, int rt) {
        const uint32_t base = sb + 16384 + stg * 16384;
        const int r0 = rt * 64;
#pragma unroll
        for (int g = 0; g < 4; g++) {
            const int i = g * 128 + tid;
            const int row = i >> 3, c = i & 7;
            const uint32_t sw = (uint32_t)row * 128 + (uint32_t)((c ^ (row & 7)) * 16);
            const size_t ro = (size_t)(r0 + row) * 64 + c * 8;
            cpasync16(base + sw,        Rh + ro);
            cpasync16(base + 8192 + sw, Rl + ro);
        }
    };

#pragma unroll
    for (int g = 0; g < 4; g++) {
        const int i = g * 128 + tid;
        const int row = i >> 3, c = i & 7;
        const uint32_t sw = (uint32_t)row * 128 + (uint32_t)((c ^ (row & 7)) * 16);
        const size_t qo = (size_t)(bb * 1024 + q0 + row) * EDIM + hh * 64 + c * 8;
        cpasync16(sb + sw,        Qbh + qo);
        cpasync16(sb + 8192 + sw, Qbl + qo);
    }
    issueR(0, 0);
    CP_COMMIT();

    uint32_t qh[4][2][4], qlr[4][2][4];
    bool qloaded = false;
    const int gid = lane >> 2, tig = lane & 3;
    float* btj = Bt + (size_t)jslot * 1024 * RSTR;

    for (int rt = 0; rt < 5; rt++) {
        if (rt + 1 < 5) { issueR((rt + 1) & 1, rt + 1); CP_COMMIT(); }
        if (rt < 4) { CP_WAIT(1); } else { CP_WAIT(0); }
        __syncthreads();

        if (!qloaded) {
            qloaded = true;
#pragma unroll
            for (int dd = 0; dd < 4; dd++)
#pragma unroll
                for (int mf = 0; mf < 2; mf++) {
                    const int row = wm * 32 + mf * 16 + arow;
                    const uint32_t addr = sb + (uint32_t)row * 128 +
                                          (uint32_t)(((dd * 2 + ahalf) ^ (row & 7)) * 16);
                    ldsm4(qh[dd][mf], addr);
                    ldsm4(qlr[dd][mf], addr + 8192);
                }
        }

        const uint32_t rbuf = sb + 16384 + (rt & 1) * 16384;
        float s[2][4][4];
#pragma unroll
        for (int mf = 0; mf < 2; mf++)
#pragma unroll
            for (int nf = 0; nf < 4; nf++)
#pragma unroll
                for (int e = 0; e < 4; e++) s[mf][nf][e] = 0.f;

#pragma unroll
        for (int dd = 0; dd < 4; dd++) {
            uint32_t bh[2][4], bl[2][4];
#pragma unroll
            for (int ng = 0; ng < 2; ng++) {
                const int row = wn * 32 + ng * 16 + arow;
                const uint32_t addr = rbuf + (uint32_t)row * 128 +
                                      (uint32_t)(((dd * 2 + ahalf) ^ (row & 7)) * 16);
                ldsm4(bh[ng], addr);
                ldsm4(bl[ng], addr + 8192);
            }
#pragma unroll
            for (int mf = 0; mf < 2; mf++)
#pragma unroll
                for (int ng = 0; ng < 2; ng++)
#pragma unroll
                    for (int h = 0; h < 2; h++) {
                        float* cc = s[mf][ng * 2 + h];
                        mma16816(cc, qh[dd][mf], bh[ng][h], bh[ng][h + 2]);
                        mma16816(cc, qh[dd][mf], bl[ng][h], bl[ng][h + 2]);
                        mma16816(cc, qlr[dd][mf], bh[ng][h], bh[ng][h + 2]);
                    }
        }
        __syncthreads();

        const int r0 = rt * 64;
#pragma unroll
        for (int mf = 0; mf < 2; mf++) {
            const int q = q0 + wm * 32 + mf * 16 + gid;
#pragma unroll
            for (int nf = 0; nf < 4; nf++) {
                const int r = r0 + wn * 32 + nf * 8 + tig * 2;
                const float* cc = s[mf][nf];
                if (r < 257) {
                    btj[(size_t)q * RSTR + r]       = cc[0];
                    btj[(size_t)(q + 8) * RSTR + r] = cc[2];
                }
                if (r + 1 < 257) {
                    btj[(size_t)q * RSTR + r + 1]       = cc[1];
                    btj[(size_t)(q + 8) * RSTR + r + 1] = cc[3];
                }
            }
        }
    }
}

// ---------------------------------------------------------------------------
// Fused relative attention, 32-row q-tile, 2 CTAs/SM, K/V single bf16.
// Round 16: exp and bucket-scatter fused into one loop.
// ---------------------------------------------------------------------------
#define ASTG 16384
#define ATT_SMEM 75264

__global__ __launch_bounds__(256, 2)
void attn2(const __nv_bfloat16* __restrict__ Qh_, const __nv_bfloat16* __restrict__ Ql_,
           const __nv_bfloat16* __restrict__ Kh_, const __nv_bfloat16* __restrict__ Vh_,
           const float* __restrict__ Bt, float* __restrict__ c1,
           __nv_bfloat16* __restrict__ A2h, __nv_bfloat16* __restrict__ A2l)
{
    extern __shared__ char smem[];
    const uint32_t sb = smem_to_u32(smem);
    float* lsum = (float*)(smem + 40960);
    float* Aa   = (float*)(smem + 41984);

    const int slot = blockIdx.y;
    const int q0 = blockIdx.x * 32;
    const int bb = slot >> 4, hh = slot & 15;
    const int jsrc = ((slot & 15) << 2) | (slot >> 4);   // sigma(slot)
    const int tid = threadIdx.x, wid = tid >> 5, lane = tid & 31;
    const int wm = wid >> 2, wn = wid & 3;               // 2(m) x 4(n)
    const int gid = lane >> 2, tig = lane & 3;
    const int arow = lane & 15, ahalf = lane >> 4;

    for (int f = tid; f < 32 * RSTR; f += 256) Aa[f] = 0.f;
    if (tid < 32) lsum[tid] = 0.f;

    auto issueKV = [&](int stg, int kt) {
        const uint32_t base = sb + 8192 + stg * ASTG;
        const int k0 = kt * 64;
#pragma unroll
        for (int g = 0; g < 2; g++) {
            const int i = g * 256 + tid;
            const int row = i >> 3, c = i & 7;
            const uint32_t sw = (uint32_t)row * 128 + (uint32_t)((c ^ (row & 7)) * 16);
            const size_t go = (size_t)(bb * 1024 + k0 + row) * EDIM + hh * 64 + c * 8;
            cpasync16(base + sw,        Kh_ + go);
            cpasync16(base + 8192 + sw, Vh_ + go);
        }
    };

    {
        const int i = tid;
        const int row = i >> 3, c = i & 7;
        const uint32_t sw = (uint32_t)row * 128 + (uint32_t)((c ^ (row & 7)) * 16);
        const size_t go = (size_t)(bb * 1024 + q0 + row) * EDIM + hh * 64 + c * 8;
        cpasync16(sb + sw,        Qh_ + go);
        cpasync16(sb + 4096 + sw, Ql_ + go);
    }
    issueKV(0, 0);
    CP_COMMIT();
    issueKV(1, 1);
    CP_COMMIT();

    float o[8][4];
#pragma unroll
    for (int nf = 0; nf < 8; nf++)
#pragma unroll
        for (int e = 0; e < 4; e++) o[nf][e] = 0.f;

    const float* btq = Bt + (size_t)jsrc * 1024 * RSTR + (size_t)q0 * RSTR;
    const int row0l = wm * 16 + gid, row1l = row0l + 8;   // 0..31

    const float bc0_lo = __ldg(&btq[(size_t)row0l * RSTR + 0]);
    const float bc0_hi = __ldg(&btq[(size_t)row0l * RSTR + 256]);
    const float bc1_lo = __ldg(&btq[(size_t)row1l * RSTR + 0]);
    const float bc1_hi = __ldg(&btq[(size_t)row1l * RSTR + 256]);
    float ls0 = 0.f, ls1 = 0.f, lo0 = 0.f, lo1 = 0.f, hi0 = 0.f, hi1 = 0.f;

    uint32_t qfh[4][4], qfl[4][4];

    for (int kt = 0; kt < 16; kt++) {
        if (kt < 15) { CP_WAIT(1); } else { CP_WAIT(0); }
        __syncthreads();
        if (kt == 0) {
#pragma unroll
            for (int dd = 0; dd < 4; dd++) {
                const int row = wm * 16 + arow;
                const uint32_t qa = sb + (uint32_t)row * 128 +
                                    (uint32_t)(((dd * 2 + ahalf) ^ (row & 7)) * 16);
                ldsm4(qfh[dd], qa);
                ldsm4(qfl[dd], qa + 4096);
            }
        }
        const uint32_t st = sb + 8192 + (kt & 1) * ASTG;
        const int k0 = kt * 64;
        const int delta = q0 - k0;

        // ---- S = (Qh+Ql) K^T  (K single bf16) ----
        float s[2][4];
        s[0][0] = s[0][1] = s[0][2] = s[0][3] = 0.f;
        s[1][0] = s[1][1] = s[1][2] = s[1][3] = 0.f;
#pragma unroll
        for (int dd = 0; dd < 4; dd++) {
            uint32_t kh[4];
            const int row = wn * 16 + arow;
            const uint32_t ka = st + (uint32_t)row * 128 +
                                (uint32_t)(((dd * 2 + ahalf) ^ (row & 7)) * 16);
            ldsm4(kh, ka);
#pragma unroll
            for (int h = 0; h < 2; h++) {
                mma16816(s[h], qfh[dd], kh[h], kh[h + 2]);
                mma16816(s[h], qfl[dd], kh[h], kh[h + 2]);
            }
        }

        // ---- bias + exp2 + row sums + buckets (fused) ----
        float rs0 = 0.f, rs1 = 0.f;
        const bool clampHi = (delta >= 192), clampLo = (delta <= -160);
        if (clampHi || clampLo) {
            const float b0 = clampHi ? bc0_hi : bc0_lo;
            const float b1 = clampHi ? bc1_hi : bc1_lo;
#pragma unroll
            for (int h = 0; h < 2; h++)
#pragma unroll
                for (int e = 0; e < 4; e++) {
                    const float p = exp2f(s[h][e] + ((e >= 2) ? b1 : b0));
                    s[h][e] = p;
                    if (e >= 2) rs1 += p; else rs0 += p;
                }
            if (clampHi) { hi0 += rs0; hi1 += rs1; }
            else         { lo0 += rs0; lo1 += rs1; }
        } else {
#pragma unroll
            for (int h = 0; h < 2; h++) {
                const int kg = k0 + wn * 16 + h * 8 + tig * 2;
#pragma unroll
                for (int e = 0; e < 4; e++) {
                    const int ql2 = (e >= 2) ? row1l : row0l;
                    const int dist = (q0 + ql2) - (kg + (e & 1));
                    const int r = dist < -128 ? 0 : (dist > 128 ? 256 : dist + 128);
                    const float p = exp2f(s[h][e] + __ldg(&btq[(size_t)ql2 * RSTR + r]));
                    s[h][e] = p;
                    if (e >= 2) rs1 += p; else rs0 += p;
                    atomicAdd(&Aa[ql2 * RSTR + r], p);
                }
            }
        }
        ls0 += rs0; ls1 += rs1;

        // ---- P -> bf16 split A-frag ----
        uint32_t pah[4], pal[4];
#pragma unroll
        for (int a = 0; a < 4; a++) {
            const int h = a >> 1, eb = (a & 1) * 2;
            const float p0 = s[h][eb], p1 = s[h][eb + 1];
            const __nv_bfloat16 h0 = __float2bfloat16(p0), h1 = __float2bfloat16(p1);
            pah[a] = pack_bf2(h0, h1);
            pal[a] = pack_bf2(__float2bfloat16(p0 - __bfloat162float(h0)),
                              __float2bfloat16(p1 - __bfloat162float(h1)));
        }

        // ---- O += (Ph+Pl) V  (V single bf16) ----
#pragma unroll
        for (int g = 0; g < 4; g++) {
            uint32_t vh[4];
            const int krow = wn * 16 + arow;
            const uint32_t va = st + 8192 + (uint32_t)krow * 128 +
                                (uint32_t)(((g * 2 + ahalf) ^ (krow & 7)) * 16);
            ldsm4t(vh, va);
#pragma unroll
            for (int h = 0; h < 2; h++) {
                float* cc = o[g * 2 + h];
                mma16816(cc, pah, vh[h * 2], vh[h * 2 + 1]);
                mma16816(cc, pal, vh[h * 2], vh[h * 2 + 1]);
            }
        }
        __syncthreads();
        if (kt + 2 < 16) { issueKV(kt & 1, kt + 2); CP_COMMIT(); }
    }

    // ---- flush deferred reductions ----
    ls0 += __shfl_xor_sync(0xffffffffu, ls0, 1); ls0 += __shfl_xor_sync(0xffffffffu, ls0, 2);
    ls1 += __shfl_xor_sync(0xffffffffu, ls1, 1); ls1 += __shfl_xor_sync(0xffffffffu, ls1, 2);
    lo0 += __shfl_xor_sync(0xffffffffu, lo0, 1); lo0 += __shfl_xor_sync(0xffffffffu, lo0, 2);
    lo1 += __shfl_xor_sync(0xffffffffu, lo1, 1); lo1 += __shfl_xor_sync(0xffffffffu, lo1, 2);
    hi0 += __shfl_xor_sync(0xffffffffu, hi0, 1); hi0 += __shfl_xor_sync(0xffffffffu, hi0, 2);
    hi1 += __shfl_xor_sync(0xffffffffu, hi1, 1); hi1 += __shfl_xor_sync(0xffffffffu, hi1, 2);
    if (tig == 0) {
        atomicAdd(&lsum[row0l], ls0);
        atomicAdd(&lsum[row1l], ls1);
        atomicAdd(&Aa[row0l * RSTR + 0], lo0);
        atomicAdd(&Aa[row1l * RSTR + 0], lo1);
        atomicAdd(&Aa[row0l * RSTR + 256], hi0);
        atomicAdd(&Aa[row1l * RSTR + 256], hi1);
    }

    // ---- epilogue: O partials to smem; invert lsum ----
    float* red = (float*)(smem + 8192);
    if (wn > 0) {
        float* rb = red + (size_t)(wn - 1) * 32 * 68;
#pragma unroll
        for (int g = 0; g < 8; g++) {
            const int col = g * 8 + tig * 2;
            *(float2*)&rb[row0l * 68 + col] = make_float2(o[g][0], o[g][1]);
            *(float2*)&rb[row1l * 68 + col] = make_float2(o[g][2], o[g][3]);
        }
    }
    __syncthreads();
    if (tid < 32) lsum[tid] = 1.f / lsum[tid];
    __syncthreads();

    // ---- w1: reduce 4 wn partials, normalize, write ----
    if (wn == 0) {
        const float inv0 = lsum[row0l];
        const float inv1 = lsum[row1l];
#pragma unroll
        for (int g = 0; g < 8; g++) {
            const int col = g * 8 + tig * 2;
            float a0 = o[g][0], a1 = o[g][1], a2 = o[g][2], a3 = o[g][3];
#pragma unroll
            for (int wv = 0; wv < 3; wv++) {
                const float* rb = red + (size_t)wv * 32 * 68;
                const float2 r0 = *(const float2*)&rb[row0l * 68 + col];
                const float2 r1 = *(const float2*)&rb[row1l * 68 + col];
                a0 += r0.x; a1 += r0.y; a2 += r1.x; a3 += r1.y;
            }
            float2 v0 = make_float2(a0 * inv0, a1 * inv0);
            float2 v1 = make_float2(a2 * inv1, a3 * inv1);
            *(float2*)&c1[(size_t)(bb * 1024 + q0 + row0l) * EDIM + hh * 64 + col] = v0;
            *(float2*)&c1[(size_t)(bb * 1024 + q0 + row1l) * EDIM + hh * 64 + col] = v1;
        }
    }

    // ---- write A2 = (A/l) bf16 split, rows padded to ASTRIDE ----
    {
        __nv_bfloat16* a2h = A2h + ((size_t)slot * 1024 + q0) * ASTRIDE;
        __nv_bfloat16* a2l = A2l + ((size_t)slot * 1024 + q0) * ASTRIDE;
        for (int i = tid; i < 32 * (ASTRIDE / 2); i += 256) {
            const int row = i / (ASTRIDE / 2);
            const int cp2 = (i % (ASTRIDE / 2)) * 2;
            const float il = lsum[row];
            const float a0 = (cp2     < RSTR) ? Aa[row * RSTR + cp2]     * il : 0.f;
            const float a1 = (cp2 + 1 < RSTR) ? Aa[row * RSTR + cp2 + 1] * il : 0.f;
            const __nv_bfloat16 h0 = __float2bfloat16(a0), h1 = __float2bfloat16(a1);
            *(uint32_t*)(a2h + (size_t)row * ASTRIDE + cp2) = pack_bf2(h0, h1);
            *(uint32_t*)(a2l + (size_t)row * ASTRIDE + cp2) =
                pack_bf2(__float2bfloat16(a0 - __bfloat162float(h0)),
                         __float2bfloat16(a1 - __bfloat162float(h1)));
        }
    }
}

// ---------------------------------------------------------------------------
extern "C" void kernel_launch(void* const* d_in, const int* in_sizes, int n_in,
                              void* d_out, int out_size)
{
    const float* X    = (const float*)d_in[0];
    const float* Wq   = (const float*)d_in[1];
    const float* bq   = (const float*)d_in[2];
    const float* Wk   = (const float*)d_in[3];
    const float* bk   = (const float*)d_in[4];
    const float* Wv   = (const float*)d_in[5];
    const float* bv   = (const float*)d_in[6];
    const float* Wo   = (const float*)d_in[7];
    const float* bo   = (const float*)d_in[8];
    const float* relk = (const float*)d_in[9];
    const float* relv = (const float*)d_in[10];
    float* out = (float*)d_out;

    float *pB, *pc1;
    cudaGetSymbolAddress((void**)&pB,  g_B);
    cudaGetSymbolAddress((void**)&pc1, g_c1);
    __nv_bfloat16 *pXh, *pXl, *pWqh, *pWql, *pWkh, *pWkl, *pWvh, *pWvl, *pWoh, *pWol;
    __nv_bfloat16 *pQbh, *pQbl, *pKbh, *pVbh, *pRkh, *pRkl, *pRvh, *pRvl, *pA2h, *pA2l;
    cudaGetSymbolAddress((void**)&pXh,  g_Xh);
    cudaGetSymbolAddress((void**)&pXl,  g_Xl);
    cudaGetSymbolAddress((void**)&pWqh, g_Wqh);
    cudaGetSymbolAddress((void**)&pWql, g_Wql);
    cudaGetSymbolAddress((void**)&pWkh, g_Wkh);
    cudaGetSymbolAddress((void**)&pWkl, g_Wkl);
    cudaGetSymbolAddress((void**)&pWvh, g_Wvh);
    cudaGetSymbolAddress((void**)&pWvl, g_Wvl);
    cudaGetSymbolAddress((void**)&pWoh, g_Woh);
    cudaGetSymbolAddress((void**)&pWol, g_Wol);
    cudaGetSymbolAddress((void**)&pQbh, g_Qbh);
    cudaGetSymbolAddress((void**)&pQbl, g_Qbl);
    cudaGetSymbolAddress((void**)&pKbh, g_Kbh);
    cudaGetSymbolAddress((void**)&pVbh, g_Vbh);
    cudaGetSymbolAddress((void**)&pRkh, g_Rkh);
    cudaGetSymbolAddress((void**)&pRkl, g_Rkl);
    cudaGetSymbolAddress((void**)&pRvh, g_Rvh);
    cudaGetSymbolAddress((void**)&pRvl, g_Rvl);
    cudaGetSymbolAddress((void**)&pA2h, g_A2h);
    cudaGetSymbolAddress((void**)&pA2l, g_A2l);

    CvtParams cp;
    cp.X = X; cp.Wq = Wq; cp.Wk = Wk; cp.Wv = Wv; cp.Wo = Wo; cp.relk = relk; cp.relv = relv;
    cp.Xh = pXh; cp.Xl = pXl;
    cp.Wqh = pWqh; cp.Wql = pWql; cp.Wkh = pWkh; cp.Wkl = pWkl;
    cp.Wvh = pWvh; cp.Wvl = pWvl; cp.Woh = pWoh; cp.Wol = pWol;
    cp.Rkh = pRkh; cp.Rkl = pRkl; cp.Rvh = pRvh; cp.Rvl = pRvl;
    cvt_all<<<8192 + 20 + 20, 256>>>(cp);

    cudaFuncSetAttribute(mma_gemm,  cudaFuncAttributeMaxDynamicSharedMemorySize, GSMEM);
    cudaFuncSetAttribute(mma_gemm3, cudaFuncAttributeMaxDynamicSharedMemorySize, GSMEM);

    // Q alpha = 0.125/ln2: scores and bias table in log2 units -> exp2f.
    G3Params p;
    p.Bh[0] = pWqh; p.Bl[0] = pWql; p.bias[0] = bq; p.oh[0] = pQbh; p.ol[0] = pQbl;
    p.alpha[0] = 0.125f * 1.4426950408889634f;
    p.Bh[1] = pWkh; p.Bl[1] = pWkl; p.bias[1] = bk; p.oh[1] = pKbh; p.ol[1] = nullptr;
    p.alpha[1] = 1.0f;
    p.Bh[2] = pWvh; p.Bl[2] = pWvl; p.bias[2] = bv; p.oh[2] = pVbh; p.ol[2] = nullptr;
    p.alpha[2] = 1.0f;
    mma_gemm3<<<dim3(EDIM / 128, MROWS / 128, 3), 256, GSMEM>>>(pXh, pXl, p);

    cudaFuncSetAttribute(bias_mma, cudaFuncAttributeMaxDynamicSharedMemorySize, BIAS_SMEM);
    bias_mma<<<dim3(16, 64), 128, BIAS_SMEM>>>(pQbh, pQbl, pRkh, pRkl, pB);

    cudaFuncSetAttribute(attn2, cudaFuncAttributeMaxDynamicSharedMemorySize, ATT_SMEM);
    attn2<<<dim3(32, 64), 256, ATT_SMEM>>>(pQbh, pQbl, pKbh, pVbh,
                                           pB, pc1, pA2h, pA2l);

    // w2 + (c1 + c2) -> bf16 split fused into one kernel
    cudaFuncSetAttribute(w2_gemm, cudaFuncAttributeMaxDynamicSharedMemorySize, W2_SMEM);
    w2_gemm<<<512, 256, W2_SMEM>>>(pA2h, pA2l, pRvh, pRvl, pc1, pXh, pXl);

    mma_gemm<<<dim3(EDIM / 128, MROWS / 128), 256, GSMEM>>>(pXh, pXl, pWoh, pWol, bo, out,
                                                            1.0f, nullptr, nullptr);
}

// round 17
// speedup vs baseline: 1.0672x; 1.0672x over previous
#include <cuda_runtime.h>
#include <cuda_bf16.h>
#include <cstdint>

// ---------------------------------------------------------------------------
// MultiheadRelativeAttention: B=4, T=1024, E=1024, H=16, D=64, MAX_REL=128
// Round 17: round-15 attn2 (separated exp / scatter loops, 203us proven)
// + round-16 w2_gemm fusion (c1+c2 bf16 split emitted directly, no
// cvt_add_split launch, no g_c2 buffer).
// ---------------------------------------------------------------------------

#define MROWS 4096      // B*T
#define EDIM  1024
#define RSTR  260       // padded stride for 257 relative positions
#define ASTRIDE 320     // padded K for w2 gemm

typedef unsigned long long u64t;

__device__ float g_B [64 * 1024 * RSTR];   // bias table per source slot (log2 units)
__device__ float g_c1[MROWS * EDIM];

__device__ __nv_bfloat16 g_Xh[MROWS * EDIM];
__device__ __nv_bfloat16 g_Xl[MROWS * EDIM];
__device__ __nv_bfloat16 g_Wqh[EDIM * EDIM], g_Wql[EDIM * EDIM];
__device__ __nv_bfloat16 g_Wkh[EDIM * EDIM], g_Wkl[EDIM * EDIM];
__device__ __nv_bfloat16 g_Wvh[EDIM * EDIM], g_Wvl[EDIM * EDIM];
__device__ __nv_bfloat16 g_Woh[EDIM * EDIM], g_Wol[EDIM * EDIM];
__device__ __nv_bfloat16 g_Qbh[MROWS * EDIM], g_Qbl[MROWS * EDIM];
__device__ __nv_bfloat16 g_Kbh[MROWS * EDIM];   // K single
__device__ __nv_bfloat16 g_Vbh[MROWS * EDIM];   // V single
__device__ __nv_bfloat16 g_Rkh[320 * 64], g_Rkl[320 * 64];
__device__ __nv_bfloat16 g_A2h[64 * 1024 * ASTRIDE], g_A2l[64 * 1024 * ASTRIDE];
__device__ __nv_bfloat16 g_Rvh[64 * ASTRIDE], g_Rvl[64 * ASTRIDE];

// ---------------------------------------------------------------------------
// helpers
// ---------------------------------------------------------------------------
__device__ __forceinline__ uint32_t smem_to_u32(const void* p) {
    uint32_t a;
    asm("{ .reg .u64 t; cvta.to.shared.u64 t, %1; cvt.u32.u64 %0, t; }" : "=r"(a) : "l"(p));
    return a;
}
__device__ __forceinline__ void cpasync16(uint32_t dst, const void* src) {
    asm volatile("cp.async.cg.shared.global [%0], [%1], 16;" :: "r"(dst), "l"(src));
}
#define CP_COMMIT() asm volatile("cp.async.commit_group;" ::: "memory")
#define CP_WAIT(n)  asm volatile("cp.async.wait_group %0;" :: "n"(n) : "memory")

__device__ __forceinline__ void ldsm4(uint32_t* r, uint32_t addr) {
    asm volatile("ldmatrix.sync.aligned.m8n8.x4.shared.b16 {%0,%1,%2,%3}, [%4];"
                 : "=r"(r[0]), "=r"(r[1]), "=r"(r[2]), "=r"(r[3]) : "r"(addr));
}
__device__ __forceinline__ void ldsm4t(uint32_t* r, uint32_t addr) {
    asm volatile("ldmatrix.sync.aligned.m8n8.x4.trans.shared.b16 {%0,%1,%2,%3}, [%4];"
                 : "=r"(r[0]), "=r"(r[1]), "=r"(r[2]), "=r"(r[3]) : "r"(addr));
}
__device__ __forceinline__ void mma16816(float* c, const uint32_t* a, uint32_t b0, uint32_t b1) {
    asm volatile("mma.sync.aligned.m16n8k16.row.col.f32.bf16.bf16.f32 "
                 "{%0,%1,%2,%3}, {%4,%5,%6,%7}, {%8,%9}, {%0,%1,%2,%3};"
                 : "+f"(c[0]), "+f"(c[1]), "+f"(c[2]), "+f"(c[3])
                 : "r"(a[0]), "r"(a[1]), "r"(a[2]), "r"(a[3]), "r"(b0), "r"(b1));
}
__device__ __forceinline__ uint32_t pack_bf2(__nv_bfloat16 lo, __nv_bfloat16 hi) {
    return ((uint32_t)__bfloat16_as_ushort(hi) << 16) | (uint32_t)__bfloat16_as_ushort(lo);
}

// ---------------------------------------------------------------------------
// merged input conversions
// ---------------------------------------------------------------------------
struct CvtParams {
    const float *X, *Wq, *Wk, *Wv, *Wo, *relk, *relv;
    __nv_bfloat16 *Xh, *Xl, *Wqh, *Wql, *Wkh, *Wkl, *Wvh, *Wvl, *Woh, *Wol;
    __nv_bfloat16 *Rkh, *Rkl, *Rvh, *Rvl;
};

__device__ __forceinline__ void split4(const float* __restrict__ src,
                                       __nv_bfloat16* __restrict__ hi,
                                       __nv_bfloat16* __restrict__ lo, int i)
{
    float4 v = *(const float4*)(src + i);
    __nv_bfloat16 h0 = __float2bfloat16(v.x), h1 = __float2bfloat16(v.y);
    __nv_bfloat16 h2 = __float2bfloat16(v.z), h3 = __float2bfloat16(v.w);
    ((uint32_t*)(hi + i))[0] = pack_bf2(h0, h1);
    ((uint32_t*)(hi + i))[1] = pack_bf2(h2, h3);
    ((uint32_t*)(lo + i))[0] = pack_bf2(__float2bfloat16(v.x - __bfloat162float(h0)),
                                        __float2bfloat16(v.y - __bfloat162float(h1)));
    ((uint32_t*)(lo + i))[1] = pack_bf2(__float2bfloat16(v.z - __bfloat162float(h2)),
                                        __float2bfloat16(v.w - __bfloat162float(h3)));
}

__global__ __launch_bounds__(256)
void cvt_all(CvtParams p)
{
    const int bid = blockIdx.x;
    if (bid < 4096) {
        split4(p.X, p.Xh, p.Xl, (bid * 256 + threadIdx.x) * 4);
    } else if (bid < 8192) {
        const int w = (bid - 4096) >> 10;
        const int lb = (bid - 4096) & 1023;
        const int i = (lb * 256 + threadIdx.x) * 4;
        if (w == 0)      split4(p.Wq, p.Wqh, p.Wql, i);
        else if (w == 1) split4(p.Wk, p.Wkh, p.Wkl, i);
        else if (w == 2) split4(p.Wv, p.Wvh, p.Wvl, i);
        else             split4(p.Wo, p.Woh, p.Wol, i);
    } else if (bid < 8212) {
        const int base = (bid - 8192) * 1024 + threadIdx.x * 4;
#pragma unroll
        for (int k = 0; k < 4; k++) {
            const int i = base + k;
            if (i >= 320 * 64) break;
            const int r = i >> 6, d = i & 63;
            const float v = (r < 257) ? p.relk[r * 64 + d] : 0.f;
            const __nv_bfloat16 h = __float2bfloat16(v);
            p.Rkh[i] = h;
            p.Rkl[i] = __float2bfloat16(v - __bfloat162float(h));
        }
    } else {
        const int base = (bid - 8212) * 1024 + threadIdx.x * 4;
#pragma unroll
        for (int k = 0; k < 4; k++) {
            const int i = base + k;
            if (i >= 64 * ASTRIDE) break;
            const int d = i / ASTRIDE, r = i % ASTRIDE;
            const float v = (r < 257) ? p.relv[r * 64 + d] : 0.f;
            const __nv_bfloat16 h = __float2bfloat16(v);
            p.Rvh[i] = h;
            p.Rvl[i] = __float2bfloat16(v - __bfloat162float(h));
        }
    }
}

// ---------------------------------------------------------------------------
// GEMM core (round-8 proven)
// ---------------------------------------------------------------------------
#define GSTAGE 65536
#define GSMEM  (3 * GSTAGE)

__device__ __forceinline__ void gemm_core(
    const __nv_bfloat16* __restrict__ Ah, const __nv_bfloat16* __restrict__ Al,
    const __nv_bfloat16* __restrict__ Bh, const __nv_bfloat16* __restrict__ Bl,
    const float* __restrict__ bias, float* __restrict__ C, float alpha,
    __nv_bfloat16* __restrict__ ohi, __nv_bfloat16* __restrict__ olo)
{
    extern __shared__ char smem[];
    const uint32_t sb = smem_to_u32(smem);
    const int tid = threadIdx.x;
    const int wid = tid >> 5, lane = tid & 31;
    const int wm = wid >> 1, wn = wid & 1;
    const int n0 = blockIdx.x * 128, m0 = blockIdx.y * 128;

    float acc[2][8][4];
#pragma unroll
    for (int f = 0; f < 2; f++)
#pragma unroll
        for (int nf = 0; nf < 8; nf++)
#pragma unroll
            for (int e = 0; e < 4; e++) acc[f][nf][e] = 0.f;

    auto issue = [&](int stage, int c) {
        const uint32_t tbs = sb + stage * GSTAGE;
        const int k0 = c * 64;
#pragma unroll
        for (int g = 0; g < 4; g++) {
            const int gi = g * 256 + tid;
            const int row = gi >> 3, gc = gi & 7;
            const uint32_t bo = row * 128 + gc * 16;
            const uint32_t sw = bo ^ ((bo >> 3) & 0x70);
            const size_t aoff = (size_t)(m0 + row) * EDIM + k0 + gc * 8;
            const size_t boff = (size_t)(n0 + row) * EDIM + k0 + gc * 8;
            cpasync16(tbs + sw,         Ah + aoff);
            cpasync16(tbs + 16384 + sw, Al + aoff);
            cpasync16(tbs + 32768 + sw, Bh + boff);
            cpasync16(tbs + 49152 + sw, Bl + boff);
        }
        CP_COMMIT();
    };

    issue(0, 0);
    issue(1, 1);

    const int arow = lane & 15;
    const int achk = lane >> 4;

    uint32_t fah[2][2][4], fal[2][2][4], fbh[2][4][4], fbl[2][4][4];
    auto ldfrag = [&](int buf, int kk, uint32_t st) {
        const int chS = (kk * 2 + achk) ^ (arow & 7);
#pragma unroll
        for (int f = 0; f < 2; f++) {
            const uint32_t ra = st + (uint32_t)(wm * 32 + f * 16 + arow) * 128 + chS * 16;
            ldsm4(fah[buf][f], ra);
            ldsm4(fal[buf][f], ra + 16384);
        }
#pragma unroll
        for (int nb = 0; nb < 4; nb++) {
            const uint32_t rb = st + 32768 + (uint32_t)(wn * 64 + nb * 16 + arow) * 128 + chS * 16;
            ldsm4(fbh[buf][nb], rb);
            ldsm4(fbl[buf][nb], rb + 16384);
        }
    };

    for (int c = 0; c < 16; c++) {
        if (c + 2 < 16) issue((c + 2) % 3, c + 2);
        if (c <= 13)      { CP_WAIT(2); }
        else if (c == 14) { CP_WAIT(1); }
        else              { CP_WAIT(0); }
        __syncthreads();

        const uint32_t st = sb + (c % 3) * GSTAGE;
        ldfrag(0, 0, st);
#pragma unroll
        for (int kk = 0; kk < 4; kk++) {
            const int cur = kk & 1;
            if (kk < 3) ldfrag(cur ^ 1, kk + 1, st);
#pragma unroll
            for (int f = 0; f < 2; f++)
#pragma unroll
                for (int nb = 0; nb < 4; nb++)
#pragma unroll
                    for (int h = 0; h < 2; h++) {
                        float* cc = acc[f][nb * 2 + h];
                        mma16816(cc, fah[cur][f], fbh[cur][nb][h], fbh[cur][nb][h + 2]);
                        mma16816(cc, fah[cur][f], fbl[cur][nb][h], fbl[cur][nb][h + 2]);
                        mma16816(cc, fal[cur][f], fbh[cur][nb][h], fbh[cur][nb][h + 2]);
                    }
        }
        __syncthreads();
    }

    const int gid = lane >> 2, tig = lane & 3;
#pragma unroll
    for (int f = 0; f < 2; f++) {
        const int m = m0 + wm * 32 + f * 16 + gid;
#pragma unroll
        for (int nb = 0; nb < 4; nb++)
#pragma unroll
            for (int h = 0; h < 2; h++) {
                const int n = n0 + wn * 64 + nb * 16 + h * 8 + tig * 2;
                const float* cc = acc[f][nb * 2 + h];
                const float b0 = __ldg(&bias[n]), b1 = __ldg(&bias[n + 1]);
                float2 v0 = make_float2(alpha * (cc[0] + b0), alpha * (cc[1] + b1));
                float2 v1 = make_float2(alpha * (cc[2] + b0), alpha * (cc[3] + b1));
                if (C) {
                    *(float2*)&C[(size_t)m * EDIM + n]       = v0;
                    *(float2*)&C[(size_t)(m + 8) * EDIM + n] = v1;
                }
                __nv_bfloat16 h00 = __float2bfloat16(v0.x), h01 = __float2bfloat16(v0.y);
                __nv_bfloat16 h10 = __float2bfloat16(v1.x), h11 = __float2bfloat16(v1.y);
                if (ohi) {
                    *(uint32_t*)(ohi + (size_t)m * EDIM + n)       = pack_bf2(h00, h01);
                    *(uint32_t*)(ohi + (size_t)(m + 8) * EDIM + n) = pack_bf2(h10, h11);
                }
                if (olo) {
                    *(uint32_t*)(olo + (size_t)m * EDIM + n) =
                        pack_bf2(__float2bfloat16(v0.x - __bfloat162float(h00)),
                                 __float2bfloat16(v0.y - __bfloat162float(h01)));
                    *(uint32_t*)(olo + (size_t)(m + 8) * EDIM + n) =
                        pack_bf2(__float2bfloat16(v1.x - __bfloat162float(h10)),
                                 __float2bfloat16(v1.y - __bfloat162float(h11)));
                }
            }
    }
}

__global__ __launch_bounds__(256, 1)
void mma_gemm(const __nv_bfloat16* __restrict__ Ah, const __nv_bfloat16* __restrict__ Al,
              const __nv_bfloat16* __restrict__ Bh, const __nv_bfloat16* __restrict__ Bl,
              const float* __restrict__ bias, float* __restrict__ C, float alpha,
              __nv_bfloat16* __restrict__ ohi, __nv_bfloat16* __restrict__ olo)
{
    gemm_core(Ah, Al, Bh, Bl, bias, C, alpha, ohi, olo);
}

struct G3Params {
    const __nv_bfloat16* Bh[3]; const __nv_bfloat16* Bl[3];
    const float* bias[3];
    __nv_bfloat16* oh[3]; __nv_bfloat16* ol[3];
    float alpha[3];
};
__global__ __launch_bounds__(256, 1)
void mma_gemm3(const __nv_bfloat16* __restrict__ Ah, const __nv_bfloat16* __restrict__ Al,
               G3Params p)
{
    const int z = blockIdx.z;
    gemm_core(Ah, Al, p.Bh[z], p.Bl[z], p.bias[z], nullptr, p.alpha[z], p.oh[z], p.ol[z]);
}

// ---------------------------------------------------------------------------
// w2_gemm: c2 = A2 @ Rvt^T, fused with (c1 + c2) -> bf16 split (Wo inputs).
// ---------------------------------------------------------------------------
#define W2_AOFF  81920
#define W2_SMEM  (81920 + 2 * 32768)   // 147456

__global__ __launch_bounds__(256, 1)
void w2_gemm(const __nv_bfloat16* __restrict__ A2h, const __nv_bfloat16* __restrict__ A2l,
             const __nv_bfloat16* __restrict__ Rvh, const __nv_bfloat16* __restrict__ Rvl,
             const float* __restrict__ c1,
             __nv_bfloat16* __restrict__ ohi, __nv_bfloat16* __restrict__ olo)
{
    extern __shared__ char smem[];
    const uint32_t sb = smem_to_u32(smem);
    const int tid = threadIdx.x;
    const int wid = tid >> 5, lane = tid & 31;
    const int wm = wid >> 1, wn = wid & 1;
    const int m0 = blockIdx.x * 128;
    const int arow = lane & 15, achk = lane >> 4;

    auto issueA = [&](int stage, int c) {
        const uint32_t base = sb + W2_AOFF + stage * 32768;
#pragma unroll
        for (int g = 0; g < 4; g++) {
            const int gi = g * 256 + tid;
            const int row = gi >> 3, gc = gi & 7;
            const uint32_t bo = row * 128 + gc * 16;
            const uint32_t sw = bo ^ ((bo >> 3) & 0x70);
            const size_t off = (size_t)(m0 + row) * ASTRIDE + c * 64 + gc * 8;
            cpasync16(base + sw,         A2h + off);
            cpasync16(base + 16384 + sw, A2l + off);
        }
    };

#pragma unroll
    for (int c = 0; c < 5; c++) {
#pragma unroll
        for (int g = 0; g < 2; g++) {
            const int gi = g * 256 + tid;
            const int row = gi >> 3, gc = gi & 7;
            const uint32_t bo = row * 128 + gc * 16;
            const uint32_t sw = bo ^ ((bo >> 3) & 0x70);
            const size_t off = (size_t)row * ASTRIDE + c * 64 + gc * 8;
            cpasync16(sb + c * 16384 + sw,        Rvh + off);
            cpasync16(sb + c * 16384 + 8192 + sw, Rvl + off);
        }
    }
    issueA(0, 0);
    CP_COMMIT();
    issueA(1, 1);
    CP_COMMIT();

    float acc[2][4][4];
#pragma unroll
    for (int f = 0; f < 2; f++)
#pragma unroll
        for (int nf = 0; nf < 4; nf++)
#pragma unroll
            for (int e = 0; e < 4; e++) acc[f][nf][e] = 0.f;

    for (int c = 0; c < 5; c++) {
        if (c < 4) { CP_WAIT(1); } else { CP_WAIT(0); }
        __syncthreads();
        const uint32_t stA = sb + W2_AOFF + (c & 1) * 32768;
        const uint32_t stB = sb + c * 16384;
#pragma unroll
        for (int kk = 0; kk < 4; kk++) {
            const int chS = (kk * 2 + achk) ^ (arow & 7);
            uint32_t ah[2][4], al[2][4], bh[2][4], bl[2][4];
#pragma unroll
            for (int f = 0; f < 2; f++) {
                const uint32_t ra = stA + (uint32_t)(wm * 32 + f * 16 + arow) * 128 + chS * 16;
                ldsm4(ah[f], ra);
                ldsm4(al[f], ra + 16384);
            }
#pragma unroll
            for (int nb = 0; nb < 2; nb++) {
                const uint32_t rb = stB + (uint32_t)(wn * 32 + nb * 16 + arow) * 128 + chS * 16;
                ldsm4(bh[nb], rb);
                ldsm4(bl[nb], rb + 8192);
            }
#pragma unroll
            for (int f = 0; f < 2; f++)
#pragma unroll
                for (int nb = 0; nb < 2; nb++)
#pragma unroll
                    for (int h = 0; h < 2; h++) {
                        float* cc = acc[f][nb * 2 + h];
                        mma16816(cc, ah[f], bh[nb][h], bh[nb][h + 2]);
                        mma16816(cc, ah[f], bl[nb][h], bl[nb][h + 2]);
                        mma16816(cc, al[f], bh[nb][h], bh[nb][h + 2]);
                    }
        }
        __syncthreads();
        if (c + 2 < 5) { issueA(c & 1, c + 2); CP_COMMIT(); }
    }

    const int gid = lane >> 2, tig = lane & 3;
#pragma unroll
    for (int f = 0; f < 2; f++) {
        const int m = m0 + wm * 32 + f * 16 + gid;
        const int slot = m >> 10, q = m & 1023;
        const int b2 = slot & 3, h2 = slot >> 2;      // sigma^-1(slot)
        const size_t row0 = (size_t)(b2 * 1024 + q) * EDIM + h2 * 64;
        const size_t row1 = (size_t)(b2 * 1024 + q + 8) * EDIM + h2 * 64;
#pragma unroll
        for (int nb = 0; nb < 2; nb++)
#pragma unroll
            for (int h = 0; h < 2; h++) {
                const int n = wn * 32 + nb * 16 + h * 8 + tig * 2;
                const float* cc = acc[f][nb * 2 + h];
                const float2 a0 = *(const float2*)&c1[row0 + n];
                const float2 a1 = *(const float2*)&c1[row1 + n];
                const float v0x = a0.x + cc[0], v0y = a0.y + cc[1];
                const float v1x = a1.x + cc[2], v1y = a1.y + cc[3];
                const __nv_bfloat16 h00 = __float2bfloat16(v0x), h01 = __float2bfloat16(v0y);
                const __nv_bfloat16 h10 = __float2bfloat16(v1x), h11 = __float2bfloat16(v1y);
                *(uint32_t*)(ohi + row0 + n) = pack_bf2(h00, h01);
                *(uint32_t*)(ohi + row1 + n) = pack_bf2(h10, h11);
                *(uint32_t*)(olo + row0 + n) =
                    pack_bf2(__float2bfloat16(v0x - __bfloat162float(h00)),
                             __float2bfloat16(v0y - __bfloat162float(h01)));
                *(uint32_t*)(olo + row1 + n) =
                    pack_bf2(__float2bfloat16(v1x - __bfloat162float(h10)),
                             __float2bfloat16(v1y - __bfloat162float(h11)));
            }
    }
}

// ---------------------------------------------------------------------------
// Bias table via mma, r-tiles looped in-CTA (round 12, unchanged)
// ---------------------------------------------------------------------------
#define BIAS_SMEM 49152
__global__ __launch_bounds__(128, 1)
void bias_mma(const __nv_bfloat16* __restrict__ Qbh, const __nv_bfloat16* __restrict__ Qbl,
              const __nv_bfloat16* __restrict__ Rh, const __nv_bfloat16* __restrict__ Rl,
              float* __restrict__ Bt)
{
    extern __shared__ char smem[];
    const uint32_t sb = smem_to_u32(smem);
    const int jslot = blockIdx.y;
    const int bb = jslot >> 4, hh = jslot & 15;
    const int q0 = blockIdx.x * 64;
    const int tid = threadIdx.x, wid = tid >> 5, lane = tid & 31;
    const int wm = wid >> 1, wn = wid & 1;
    const int arow = lane & 15, ahalf = lane >> 4;

    auto issueR = [&](int stg, int rt) {
        const uint32_t base = sb + 16384 + stg * 16384;
        const int r0 = rt * 64;
#pragma unroll
        for (int g = 0; g < 4; g++) {
            const int i = g * 128 + tid;
            const int row = i >> 3, c = i & 7;
            const uint32_t sw = (uint32_t)row * 128 + (uint32_t)((c ^ (row & 7)) * 16);
            const size_t ro = (size_t)(r0 + row) * 64 + c * 8;
            cpasync16(base + sw,        Rh + ro);
            cpasync16(base + 8192 + sw, Rl + ro);
        }
    };

#pragma unroll
    for (int g = 0; g < 4; g++) {
        const int i = g * 128 + tid;
        const int row = i >> 3, c = i & 7;
        const uint32_t sw = (uint32_t)row * 128 + (uint32_t)((c ^ (row & 7)) * 16);
        const size_t qo = (size_t)(bb * 1024 + q0 + row) * EDIM + hh * 64 + c * 8;
        cpasync16(sb + sw,        Qbh + qo);
        cpasync16(sb + 8192 + sw, Qbl + qo);
    }
    issueR(0, 0);
    CP_COMMIT();

    uint32_t qh[4][2][4], qlr[4][2][4];
    bool qloaded = false;
    const int gid = lane >> 2, tig = lane & 3;
    float* btj = Bt + (size_t)jslot * 1024 * RSTR;

    for (int rt = 0; rt < 5; rt++) {
        if (rt + 1 < 5) { issueR((rt + 1) & 1, rt + 1); CP_COMMIT(); }
        if (rt < 4) { CP_WAIT(1); } else { CP_WAIT(0); }
        __syncthreads();

        if (!qloaded) {
            qloaded = true;
#pragma unroll
            for (int dd = 0; dd < 4; dd++)
#pragma unroll
                for (int mf = 0; mf < 2; mf++) {
                    const int row = wm * 32 + mf * 16 + arow;
                    const uint32_t addr = sb + (uint32_t)row * 128 +
                                          (uint32_t)(((dd * 2 + ahalf) ^ (row & 7)) * 16);
                    ldsm4(qh[dd][mf], addr);
                    ldsm4(qlr[dd][mf], addr + 8192);
                }
        }

        const uint32_t rbuf = sb + 16384 + (rt & 1) * 16384;
        float s[2][4][4];
#pragma unroll
        for (int mf = 0; mf < 2; mf++)
#pragma unroll
            for (int nf = 0; nf < 4; nf++)
#pragma unroll
                for (int e = 0; e < 4; e++) s[mf][nf][e] = 0.f;

#pragma unroll
        for (int dd = 0; dd < 4; dd++) {
            uint32_t bh[2][4], bl[2][4];
#pragma unroll
            for (int ng = 0; ng < 2; ng++) {
                const int row = wn * 32 + ng * 16 + arow;
                const uint32_t addr = rbuf + (uint32_t)row * 128 +
                                      (uint32_t)(((dd * 2 + ahalf) ^ (row & 7)) * 16);
                ldsm4(bh[ng], addr);
                ldsm4(bl[ng], addr + 8192);
            }
#pragma unroll
            for (int mf = 0; mf < 2; mf++)
#pragma unroll
                for (int ng = 0; ng < 2; ng++)
#pragma unroll
                    for (int h = 0; h < 2; h++) {
                        float* cc = s[mf][ng * 2 + h];
                        mma16816(cc, qh[dd][mf], bh[ng][h], bh[ng][h + 2]);
                        mma16816(cc, qh[dd][mf], bl[ng][h], bl[ng][h + 2]);
                        mma16816(cc, qlr[dd][mf], bh[ng][h], bh[ng][h + 2]);
                    }
        }
        __syncthreads();

        const int r0 = rt * 64;
#pragma unroll
        for (int mf = 0; mf < 2; mf++) {
            const int q = q0 + wm * 32 + mf * 16 + gid;
#pragma unroll
            for (int nf = 0; nf < 4; nf++) {
                const int r = r0 + wn * 32 + nf * 8 + tig * 2;
                const float* cc = s[mf][nf];
                if (r < 257) {
                    btj[(size_t)q * RSTR + r]       = cc[0];
                    btj[(size_t)(q + 8) * RSTR + r] = cc[2];
                }
                if (r + 1 < 257) {
                    btj[(size_t)q * RSTR + r + 1]       = cc[1];
                    btj[(size_t)(q + 8) * RSTR + r + 1] = cc[3];
                }
            }
        }
    }
}

// ---------------------------------------------------------------------------
// Fused relative attention, 32-row q-tile, 2 CTAs/SM, K/V single bf16.
// Round-15 proven structure: separate exp loop then separate scatter loop.
// ---------------------------------------------------------------------------
#define ASTG 16384
#define ATT_SMEM 75264

__global__ __launch_bounds__(256, 2)
void attn2(const __nv_bfloat16* __restrict__ Qh_, const __nv_bfloat16* __restrict__ Ql_,
           const __nv_bfloat16* __restrict__ Kh_, const __nv_bfloat16* __restrict__ Vh_,
           const float* __restrict__ Bt, float* __restrict__ c1,
           __nv_bfloat16* __restrict__ A2h, __nv_bfloat16* __restrict__ A2l)
{
    extern __shared__ char smem[];
    const uint32_t sb = smem_to_u32(smem);
    float* lsum = (float*)(smem + 40960);
    float* Aa   = (float*)(smem + 41984);

    const int slot = blockIdx.y;
    const int q0 = blockIdx.x * 32;
    const int bb = slot >> 4, hh = slot & 15;
    const int jsrc = ((slot & 15) << 2) | (slot >> 4);   // sigma(slot)
    const int tid = threadIdx.x, wid = tid >> 5, lane = tid & 31;
    const int wm = wid >> 2, wn = wid & 3;               // 2(m) x 4(n)
    const int gid = lane >> 2, tig = lane & 3;
    const int arow = lane & 15, ahalf = lane >> 4;

    for (int f = tid; f < 32 * RSTR; f += 256) Aa[f] = 0.f;
    if (tid < 32) lsum[tid] = 0.f;

    auto issueKV = [&](int stg, int kt) {
        const uint32_t base = sb + 8192 + stg * ASTG;
        const int k0 = kt * 64;
#pragma unroll
        for (int g = 0; g < 2; g++) {
            const int i = g * 256 + tid;
            const int row = i >> 3, c = i & 7;
            const uint32_t sw = (uint32_t)row * 128 + (uint32_t)((c ^ (row & 7)) * 16);
            const size_t go = (size_t)(bb * 1024 + k0 + row) * EDIM + hh * 64 + c * 8;
            cpasync16(base + sw,        Kh_ + go);
            cpasync16(base + 8192 + sw, Vh_ + go);
        }
    };

    {
        const int i = tid;
        const int row = i >> 3, c = i & 7;
        const uint32_t sw = (uint32_t)row * 128 + (uint32_t)((c ^ (row & 7)) * 16);
        const size_t go = (size_t)(bb * 1024 + q0 + row) * EDIM + hh * 64 + c * 8;
        cpasync16(sb + sw,        Qh_ + go);
        cpasync16(sb + 4096 + sw, Ql_ + go);
    }
    issueKV(0, 0);
    CP_COMMIT();
    issueKV(1, 1);
    CP_COMMIT();

    float o[8][4];
#pragma unroll
    for (int nf = 0; nf < 8; nf++)
#pragma unroll
        for (int e = 0; e < 4; e++) o[nf][e] = 0.f;

    const float* btq = Bt + (size_t)jsrc * 1024 * RSTR + (size_t)q0 * RSTR;
    const int row0l = wm * 16 + gid, row1l = row0l + 8;   // 0..31

    const float bc0_lo = __ldg(&btq[(size_t)row0l * RSTR + 0]);
    const float bc0_hi = __ldg(&btq[(size_t)row0l * RSTR + 256]);
    const float bc1_lo = __ldg(&btq[(size_t)row1l * RSTR + 0]);
    const float bc1_hi = __ldg(&btq[(size_t)row1l * RSTR + 256]);
    float ls0 = 0.f, ls1 = 0.f, lo0 = 0.f, lo1 = 0.f, hi0 = 0.f, hi1 = 0.f;

    uint32_t qfh[4][4], qfl[4][4];

    for (int kt = 0; kt < 16; kt++) {
        if (kt < 15) { CP_WAIT(1); } else { CP_WAIT(0); }
        __syncthreads();
        if (kt == 0) {
#pragma unroll
            for (int dd = 0; dd < 4; dd++) {
                const int row = wm * 16 + arow;
                const uint32_t qa = sb + (uint32_t)row * 128 +
                                    (uint32_t)(((dd * 2 + ahalf) ^ (row & 7)) * 16);
                ldsm4(qfh[dd], qa);
                ldsm4(qfl[dd], qa + 4096);
            }
        }
        const uint32_t st = sb + 8192 + (kt & 1) * ASTG;
        const int k0 = kt * 64;
        const int delta = q0 - k0;

        // ---- S = (Qh+Ql) K^T  (K single bf16) ----
        float s[2][4];
        s[0][0] = s[0][1] = s[0][2] = s[0][3] = 0.f;
        s[1][0] = s[1][1] = s[1][2] = s[1][3] = 0.f;
#pragma unroll
        for (int dd = 0; dd < 4; dd++) {
            uint32_t kh[4];
            const int row = wn * 16 + arow;
            const uint32_t ka = st + (uint32_t)row * 128 +
                                (uint32_t)(((dd * 2 + ahalf) ^ (row & 7)) * 16);
            ldsm4(kh, ka);
#pragma unroll
            for (int h = 0; h < 2; h++) {
                mma16816(s[h], qfh[dd], kh[h], kh[h + 2]);
                mma16816(s[h], qfl[dd], kh[h], kh[h + 2]);
            }
        }

        // ---- bias + exp2 + row sums; then separate bucket scatter ----
        float rs0 = 0.f, rs1 = 0.f;
        const bool clampHi = (delta >= 192), clampLo = (delta <= -160);
        if (clampHi || clampLo) {
            const float b0 = clampHi ? bc0_hi : bc0_lo;
            const float b1 = clampHi ? bc1_hi : bc1_lo;
#pragma unroll
            for (int h = 0; h < 2; h++)
#pragma unroll
                for (int e = 0; e < 4; e++) {
                    const float p = exp2f(s[h][e] + ((e >= 2) ? b1 : b0));
                    s[h][e] = p;
                    if (e >= 2) rs1 += p; else rs0 += p;
                }
            if (clampHi) { hi0 += rs0; hi1 += rs1; }
            else         { lo0 += rs0; lo1 += rs1; }
        } else {
#pragma unroll
            for (int h = 0; h < 2; h++) {
                const int kg = k0 + wn * 16 + h * 8 + tig * 2;
#pragma unroll
                for (int e = 0; e < 4; e++) {
                    const int ql2 = (e >= 2) ? row1l : row0l;
                    const int dist = (q0 + ql2) - (kg + (e & 1));
                    const int r = dist < -128 ? 0 : (dist > 128 ? 256 : dist + 128);
                    const float p = exp2f(s[h][e] + __ldg(&btq[(size_t)ql2 * RSTR + r]));
                    s[h][e] = p;
                    if (e >= 2) rs1 += p; else rs0 += p;
                }
            }
#pragma unroll
            for (int h = 0; h < 2; h++) {
                const int kg = k0 + wn * 16 + h * 8 + tig * 2;
#pragma unroll
                for (int e = 0; e < 4; e++) {
                    const int ql2 = (e >= 2) ? row1l : row0l;
                    const int dist = (q0 + ql2) - (kg + (e & 1));
                    const int r = dist < -128 ? 0 : (dist > 128 ? 256 : dist + 128);
                    atomicAdd(&Aa[ql2 * RSTR + r], s[h][e]);
                }
            }
        }
        ls0 += rs0; ls1 += rs1;

        // ---- P -> bf16 split A-frag ----
        uint32_t pah[4], pal[4];
#pragma unroll
        for (int a = 0; a < 4; a++) {
            const int h = a >> 1, eb = (a & 1) * 2;
            const float p0 = s[h][eb], p1 = s[h][eb + 1];
            const __nv_bfloat16 h0 = __float2bfloat16(p0), h1 = __float2bfloat16(p1);
            pah[a] = pack_bf2(h0, h1);
            pal[a] = pack_bf2(__float2bfloat16(p0 - __bfloat162float(h0)),
                              __float2bfloat16(p1 - __bfloat162float(h1)));
        }

        // ---- O += (Ph+Pl) V  (V single bf16) ----
#pragma unroll
        for (int g = 0; g < 4; g++) {
            uint32_t vh[4];
            const int krow = wn * 16 + arow;
            const uint32_t va = st + 8192 + (uint32_t)krow * 128 +
                                (uint32_t)(((g * 2 + ahalf) ^ (krow & 7)) * 16);
            ldsm4t(vh, va);
#pragma unroll
            for (int h = 0; h < 2; h++) {
                float* cc = o[g * 2 + h];
                mma16816(cc, pah, vh[h * 2], vh[h * 2 + 1]);
                mma16816(cc, pal, vh[h * 2], vh[h * 2 + 1]);
            }
        }
        __syncthreads();
        if (kt + 2 < 16) { issueKV(kt & 1, kt + 2); CP_COMMIT(); }
    }

    // ---- flush deferred reductions ----
    ls0 += __shfl_xor_sync(0xffffffffu, ls0, 1); ls0 += __shfl_xor_sync(0xffffffffu, ls0, 2);
    ls1 += __shfl_xor_sync(0xffffffffu, ls1, 1); ls1 += __shfl_xor_sync(0xffffffffu, ls1, 2);
    lo0 += __shfl_xor_sync(0xffffffffu, lo0, 1); lo0 += __shfl_xor_sync(0xffffffffu, lo0, 2);
    lo1 += __shfl_xor_sync(0xffffffffu, lo1, 1); lo1 += __shfl_xor_sync(0xffffffffu, lo1, 2);
    hi0 += __shfl_xor_sync(0xffffffffu, hi0, 1); hi0 += __shfl_xor_sync(0xffffffffu, hi0, 2);
    hi1 += __shfl_xor_sync(0xffffffffu, hi1, 1); hi1 += __shfl_xor_sync(0xffffffffu, hi1, 2);
    if (tig == 0) {
        atomicAdd(&lsum[row0l], ls0);
        atomicAdd(&lsum[row1l], ls1);
        atomicAdd(&Aa[row0l * RSTR + 0], lo0);
        atomicAdd(&Aa[row1l * RSTR + 0], lo1);
        atomicAdd(&Aa[row0l * RSTR + 256], hi0);
        atomicAdd(&Aa[row1l * RSTR + 256], hi1);
    }

    // ---- epilogue: O partials to smem; invert lsum ----
    float* red = (float*)(smem + 8192);
    if (wn > 0) {
        float* rb = red + (size_t)(wn - 1) * 32 * 68;
#pragma unroll
        for (int g = 0; g < 8; g++) {
            const int col = g * 8 + tig * 2;
            *(float2*)&rb[row0l * 68 + col] = make_float2(o[g][0], o[g][1]);
            *(float2*)&rb[row1l * 68 + col] = make_float2(o[g][2], o[g][3]);
        }
    }
    __syncthreads();
    if (tid < 32) lsum[tid] = 1.f / lsum[tid];
    __syncthreads();

    // ---- w1: reduce 4 wn partials, normalize, write ----
    if (wn == 0) {
        const float inv0 = lsum[row0l];
        const float inv1 = lsum[row1l];
#pragma unroll
        for (int g = 0; g < 8; g++) {
            const int col = g * 8 + tig * 2;
            float a0 = o[g][0], a1 = o[g][1], a2 = o[g][2], a3 = o[g][3];
#pragma unroll
            for (int wv = 0; wv < 3; wv++) {
                const float* rb = red + (size_t)wv * 32 * 68;
                const float2 r0 = *(const float2*)&rb[row0l * 68 + col];
                const float2 r1 = *(const float2*)&rb[row1l * 68 + col];
                a0 += r0.x; a1 += r0.y; a2 += r1.x; a3 += r1.y;
            }
            float2 v0 = make_float2(a0 * inv0, a1 * inv0);
            float2 v1 = make_float2(a2 * inv1, a3 * inv1);
            *(float2*)&c1[(size_t)(bb * 1024 + q0 + row0l) * EDIM + hh * 64 + col] = v0;
            *(float2*)&c1[(size_t)(bb * 1024 + q0 + row1l) * EDIM + hh * 64 + col] = v1;
        }
    }

    // ---- write A2 = (A/l) bf16 split, rows padded to ASTRIDE ----
    {
        __nv_bfloat16* a2h = A2h + ((size_t)slot * 1024 + q0) * ASTRIDE;
        __nv_bfloat16* a2l = A2l + ((size_t)slot * 1024 + q0) * ASTRIDE;
        for (int i = tid; i < 32 * (ASTRIDE / 2); i += 256) {
            const int row = i / (ASTRIDE / 2);
            const int cp2 = (i % (ASTRIDE / 2)) * 2;
            const float il = lsum[row];
            const float a0 = (cp2     < RSTR) ? Aa[row * RSTR + cp2]     * il : 0.f;
            const float a1 = (cp2 + 1 < RSTR) ? Aa[row * RSTR + cp2 + 1] * il : 0.f;
            const __nv_bfloat16 h0 = __float2bfloat16(a0), h1 = __float2bfloat16(a1);
            *(uint32_t*)(a2h + (size_t)row * ASTRIDE + cp2) = pack_bf2(h0, h1);
            *(uint32_t*)(a2l + (size_t)row * ASTRIDE + cp2) =
                pack_bf2(__float2bfloat16(a0 - __bfloat162float(h0)),
                         __float2bfloat16(a1 - __bfloat162float(h1)));
        }
    }
}

// ---------------------------------------------------------------------------
extern "C" void kernel_launch(void* const* d_in, const int* in_sizes, int n_in,
                              void* d_out, int out_size)
{
    const float* X    = (const float*)d_in[0];
    const float* Wq   = (const float*)d_in[1];
    const float* bq   = (const float*)d_in[2];
    const float* Wk   = (const float*)d_in[3];
    const float* bk   = (const float*)d_in[4];
    const float* Wv   = (const float*)d_in[5];
    const float* bv   = (const float*)d_in[6];
    const float* Wo   = (const float*)d_in[7];
    const float* bo   = (const float*)d_in[8];
    const float* relk = (const float*)d_in[9];
    const float* relv = (const float*)d_in[10];
    float* out = (float*)d_out;

    float *pB, *pc1;
    cudaGetSymbolAddress((void**)&pB,  g_B);
    cudaGetSymbolAddress((void**)&pc1, g_c1);
    __nv_bfloat16 *pXh, *pXl, *pWqh, *pWql, *pWkh, *pWkl, *pWvh, *pWvl, *pWoh, *pWol;
    __nv_bfloat16 *pQbh, *pQbl, *pKbh, *pVbh, *pRkh, *pRkl, *pRvh, *pRvl, *pA2h, *pA2l;
    cudaGetSymbolAddress((void**)&pXh,  g_Xh);
    cudaGetSymbolAddress((void**)&pXl,  g_Xl);
    cudaGetSymbolAddress((void**)&pWqh, g_Wqh);
    cudaGetSymbolAddress((void**)&pWql, g_Wql);
    cudaGetSymbolAddress((void**)&pWkh, g_Wkh);
    cudaGetSymbolAddress((void**)&pWkl, g_Wkl);
    cudaGetSymbolAddress((void**)&pWvh, g_Wvh);
    cudaGetSymbolAddress((void**)&pWvl, g_Wvl);
    cudaGetSymbolAddress((void**)&pWoh, g_Woh);
    cudaGetSymbolAddress((void**)&pWol, g_Wol);
    cudaGetSymbolAddress((void**)&pQbh, g_Qbh);
    cudaGetSymbolAddress((void**)&pQbl, g_Qbl);
    cudaGetSymbolAddress((void**)&pKbh, g_Kbh);
    cudaGetSymbolAddress((void**)&pVbh, g_Vbh);
    cudaGetSymbolAddress((void**)&pRkh, g_Rkh);
    cudaGetSymbolAddress((void**)&pRkl, g_Rkl);
    cudaGetSymbolAddress((void**)&pRvh, g_Rvh);
    cudaGetSymbolAddress((void**)&pRvl, g_Rvl);
    cudaGetSymbolAddress((void**)&pA2h, g_A2h);
    cudaGetSymbolAddress((void**)&pA2l, g_A2l);

    CvtParams cp;
    cp.X = X; cp.Wq = Wq; cp.Wk = Wk; cp.Wv = Wv; cp.Wo = Wo; cp.relk = relk; cp.relv = relv;
    cp.Xh = pXh; cp.Xl = pXl;
    cp.Wqh = pWqh; cp.Wql = pWql; cp.Wkh = pWkh; cp.Wkl = pWkl;
    cp.Wvh = pWvh; cp.Wvl = pWvl; cp.Woh = pWoh; cp.Wol = pWol;
    cp.Rkh = pRkh; cp.Rkl = pRkl; cp.Rvh = pRvh; cp.Rvl = pRvl;
    cvt_all<<<8192 + 20 + 20, 256>>>(cp);

    cudaFuncSetAttribute(mma_gemm,  cudaFuncAttributeMaxDynamicSharedMemorySize, GSMEM);
    cudaFuncSetAttribute(mma_gemm3, cudaFuncAttributeMaxDynamicSharedMemorySize, GSMEM);

    // Q alpha = 0.125/ln2: scores and bias table in log2 units -> exp2f.
    G3Params p;
    p.Bh[0] = pWqh; p.Bl[0] = pWql; p.bias[0] = bq; p.oh[0] = pQbh; p.ol[0] = pQbl;
    p.alpha[0] = 0.125f * 1.4426950408889634f;
    p.Bh[1] = pWkh; p.Bl[1] = pWkl; p.bias[1] = bk; p.oh[1] = pKbh; p.ol[1] = nullptr;
    p.alpha[1] = 1.0f;
    p.Bh[2] = pWvh; p.Bl[2] = pWvl; p.bias[2] = bv; p.oh[2] = pVbh; p.ol[2] = nullptr;
    p.alpha[2] = 1.0f;
    mma_gemm3<<<dim3(EDIM / 128, MROWS / 128, 3), 256, GSMEM>>>(pXh, pXl, p);

    cudaFuncSetAttribute(bias_mma, cudaFuncAttributeMaxDynamicSharedMemorySize, BIAS_SMEM);
    bias_mma<<<dim3(16, 64), 128, BIAS_SMEM>>>(pQbh, pQbl, pRkh, pRkl, pB);

    cudaFuncSetAttribute(attn2, cudaFuncAttributeMaxDynamicSharedMemorySize, ATT_SMEM);
    attn2<<<dim3(32, 64), 256, ATT_SMEM>>>(pQbh, pQbl, pKbh, pVbh,
                                           pB, pc1, pA2h, pA2l);

    // w2 + (c1 + c2) -> bf16 split fused into one kernel
    cudaFuncSetAttribute(w2_gemm, cudaFuncAttributeMaxDynamicSharedMemorySize, W2_SMEM);
    w2_gemm<<<512, 256, W2_SMEM>>>(pA2h, pA2l, pRvh, pRvl, pc1, pXh, pXl);

    mma_gemm<<<dim3(EDIM / 128, MROWS / 128), 256, GSMEM>>>(pXh, pXl, pWoh, pWol, bo, out,
                                                            1.0f, nullptr, nullptr);
}